// round 8
// baseline (speedup 1.0000x reference)
#include <cuda_runtime.h>
#include <cuda_bf16.h>
#include <math.h>
#include <cstdint>

#define BB 4
#define TT 2048
#define CC 1024
#define HH 16
#define HD 64
#define GK 1024

// ---------------------------------------------------------------------------
// Device-global scratch (allocation-free per harness rules)
// ---------------------------------------------------------------------------
__device__ float g_q[(size_t)BB*HH*TT*HD];           // [B,H,T,HD] fp32
__device__ float g_k[(size_t)BB*HH*TT*HD];
__device__ float g_v[(size_t)BB*HH*TT*HD];
__device__ __nv_bfloat16 g_xhi[(size_t)BB*TT*CC];    // X split
__device__ __nv_bfloat16 g_xlo[(size_t)BB*TT*CC];
__device__ __nv_bfloat16 g_whi[(size_t)4*CC*CC];     // Wk,Wq,Wv,Wp split
__device__ __nv_bfloat16 g_wlo[(size_t)4*CC*CC];
__device__ __nv_bfloat16 g_yhi[(size_t)BB*TT*CC];    // attention out split
__device__ __nv_bfloat16 g_ylo[(size_t)BB*TT*CC];

// ---------------------------------------------------------------------------
// PTX helpers (sm_80+ only: mma.sync / ldmatrix / cp.async — no tcgen05)
// ---------------------------------------------------------------------------
__device__ __forceinline__ uint32_t smem_u32(const void* p) {
    uint32_t a;
    asm("{ .reg .u64 t; cvta.to.shared.u64 t, %1; cvt.u32.u64 %0, t; }" : "=r"(a) : "l"(p));
    return a;
}
__device__ __forceinline__ void ldsm4(uint32_t* r, uint32_t addr) {
    asm volatile("ldmatrix.sync.aligned.m8n8.x4.shared.b16 {%0,%1,%2,%3}, [%4];"
        : "=r"(r[0]), "=r"(r[1]), "=r"(r[2]), "=r"(r[3]) : "r"(addr));
}
__device__ __forceinline__ void mma_bf16(float* d, const uint32_t* a, const uint32_t* b) {
    asm volatile("mma.sync.aligned.m16n8k16.row.col.f32.bf16.bf16.f32 "
        "{%0,%1,%2,%3}, {%4,%5,%6,%7}, {%8,%9}, {%0,%1,%2,%3};"
        : "+f"(d[0]), "+f"(d[1]), "+f"(d[2]), "+f"(d[3])
        : "r"(a[0]), "r"(a[1]), "r"(a[2]), "r"(a[3]), "r"(b[0]), "r"(b[1]));
}
__device__ __forceinline__ void cpa16(uint32_t dst, const void* src) {
    asm volatile("cp.async.cg.shared.global [%0], [%1], 16;" :: "r"(dst), "l"(src));
}
#define CP_COMMIT() asm volatile("cp.async.commit_group;" ::: "memory")
#define CP_WAIT1()  asm volatile("cp.async.wait_group 1;" ::: "memory")
#define CP_WAIT0()  asm volatile("cp.async.wait_group 0;" ::: "memory")

// ---------------------------------------------------------------------------
// GEMM core: C[128x128] = A[128xK] * B[128xK]^T with bf16 hi/lo 3-term split.
// SMEM per stage (double-buffered): Ahi|Alo|Bhi|Blo, each 128 rows x 32 bf16,
// rows padded to 80 B (conflict-free ldmatrix). Stage = 40960 B, total 81920 B.
// 256 threads = 8 warps (wm in 0..1 -> m 64, wn in 0..3 -> n 32).
// acc[mf][nf][4]: mf 0..3 (m16), nf 0..3 (n8).
// ---------------------------------------------------------------------------
#define GSTAGE 40960
#define GSMEM  (2*GSTAGE)
#define NSTG   (GK/32)

__device__ __forceinline__ void gemm_core(
    float acc[4][4][4], char* smem,
    const __nv_bfloat16* __restrict__ Ahi, const __nv_bfloat16* __restrict__ Alo,
    const __nv_bfloat16* __restrict__ Bhi, const __nv_bfloat16* __restrict__ Blo)
{
    const int tid = threadIdx.x, lane = tid & 31, wid = tid >> 5;
    const int wm = wid >> 2, wn = wid & 3;
    const uint32_t sb = smem_u32(smem);

#pragma unroll
    for (int i = 0; i < 4; i++)
#pragma unroll
        for (int j = 0; j < 4; j++)
#pragma unroll
            for (int v = 0; v < 4; v++) acc[i][j][v] = 0.f;

    // ldmatrix lane address components
    const int laneA_row = (lane & 7) + ((lane >> 3) & 1) * 8;
    const int laneA_kb  = (lane >> 4) * 16;
    const int laneB_row = (lane & 7) + (lane >> 4) * 8;
    const int laneB_kb  = ((lane >> 3) & 1) * 16;
    const uint32_t aB0 = sb + (uint32_t)(wm * 64 + laneA_row) * 80 + laneA_kb;
    const uint32_t bB0 = sb + 20480u + (uint32_t)(wn * 32 + laneB_row) * 80 + laneB_kb;

    // cp.async mapping: thread handles rows (tid>>2) and (tid>>2)+64, seg tid&3
    const int lrow = tid >> 2, lseg = tid & 3;
    const uint32_t dst0 = sb + (uint32_t)lrow * 80 + lseg * 16;

    auto load_stage = [&](int s) {
        const uint32_t d = dst0 + (uint32_t)(s & 1) * GSTAGE;
        const size_t go  = (size_t)lrow * GK + (size_t)s * 32 + lseg * 8;
        const size_t go2 = go + (size_t)64 * GK;
        cpa16(d,                  Ahi + go);
        cpa16(d + 64*80,          Ahi + go2);
        cpa16(d + 10240,          Alo + go);
        cpa16(d + 10240 + 64*80,  Alo + go2);
        cpa16(d + 20480,          Bhi + go);
        cpa16(d + 20480 + 64*80,  Bhi + go2);
        cpa16(d + 30720,          Blo + go);
        cpa16(d + 30720 + 64*80,  Blo + go2);
        CP_COMMIT();
    };

    load_stage(0);

    for (int s = 0; s < NSTG; s++) {
        if (s + 1 < NSTG) { load_stage(s + 1); CP_WAIT1(); }
        else              { CP_WAIT0(); }
        __syncthreads();

        const uint32_t aB = aB0 + (uint32_t)(s & 1) * GSTAGE;
        const uint32_t bB = bB0 + (uint32_t)(s & 1) * GSTAGE;
#pragma unroll
        for (int kk = 0; kk < 2; kk++) {
            const uint32_t ko = kk * 32;   // 16 bf16 = 32 B
            uint32_t ah[4][4], al[4][4], bh[2][4], bl[2][4];
#pragma unroll
            for (int mf = 0; mf < 4; mf++) {
                ldsm4(ah[mf], aB + mf * 1280 + ko);
                ldsm4(al[mf], aB + 10240 + mf * 1280 + ko);
            }
#pragma unroll
            for (int p = 0; p < 2; p++) {
                ldsm4(bh[p], bB + p * 1280 + ko);
                ldsm4(bl[p], bB + 10240 + p * 1280 + ko);
            }
#pragma unroll
            for (int mf = 0; mf < 4; mf++)
#pragma unroll
                for (int nf = 0; nf < 4; nf++) {
                    uint32_t* ph = &bh[nf >> 1][(nf & 1) * 2];
                    uint32_t* pl = &bl[nf >> 1][(nf & 1) * 2];
                    mma_bf16(acc[mf][nf], ah[mf], ph);   // hi*hi
                    mma_bf16(acc[mf][nf], al[mf], ph);   // lo*hi
                    mma_bf16(acc[mf][nf], ah[mf], pl);   // hi*lo
                }
        }
        __syncthreads();
    }
}

// ---------------------------------------------------------------------------
// GEMM A: fused QKV. grid (8, 64, 3) x 256. Scatter to [B,H,T,HD] fp32 + bias.
// ---------------------------------------------------------------------------
__global__ __launch_bounds__(256, 1)
void qkv_mma_kernel(const float* __restrict__ bk, const float* __restrict__ bq,
                    const float* __restrict__ bv)
{
    extern __shared__ char smem[];
    const int z = blockIdx.z;
    const float* bias; float* out;
    if (z == 0)      { bias = bk; out = g_k; }
    else if (z == 1) { bias = bq; out = g_q; }
    else             { bias = bv; out = g_v; }

    const int mBase = blockIdx.y << 7;
    const int nBase = blockIdx.x << 7;

    float acc[4][4][4];
    gemm_core(acc, smem,
        g_xhi + (size_t)mBase * GK, g_xlo + (size_t)mBase * GK,
        g_whi + (size_t)z * CC * CC + (size_t)nBase * GK,
        g_wlo + (size_t)z * CC * CC + (size_t)nBase * GK);

    const int lane = threadIdx.x & 31, wid = threadIdx.x >> 5;
    const int wm = wid >> 2, wn = wid & 3;
    const int er = lane >> 2, ec = (lane & 3) * 2;
#pragma unroll
    for (int mf = 0; mf < 4; mf++)
#pragma unroll
        for (int nf = 0; nf < 4; nf++)
#pragma unroll
            for (int hh = 0; hh < 2; hh++) {
                const int m = mBase + wm*64 + mf*16 + er + hh*8;
                const int n = nBase + wn*32 + nf*8 + ec;
                const int bb = m >> 11, t = m & (TT - 1);
                const int hd = n >> 6, d = n & 63;
                float2 o;
                o.x = acc[mf][nf][hh*2+0] + bias[n];
                o.y = acc[mf][nf][hh*2+1] + bias[n+1];
                *(float2*)&out[(((size_t)bb*HH + hd)*TT + t)*HD + d] = o;
            }
}

// ---------------------------------------------------------------------------
// GEMM B: output projection. grid (8, 64) x 256. Writes d_out + bias.
// ---------------------------------------------------------------------------
__global__ __launch_bounds__(256, 1)
void proj_mma_kernel(const float* __restrict__ bp, float* __restrict__ outp)
{
    extern __shared__ char smem[];
    const int mBase = blockIdx.y << 7;
    const int nBase = blockIdx.x << 7;

    float acc[4][4][4];
    gemm_core(acc, smem,
        g_yhi + (size_t)mBase * GK, g_ylo + (size_t)mBase * GK,
        g_whi + (size_t)3 * CC * CC + (size_t)nBase * GK,
        g_wlo + (size_t)3 * CC * CC + (size_t)nBase * GK);

    const int lane = threadIdx.x & 31, wid = threadIdx.x >> 5;
    const int wm = wid >> 2, wn = wid & 3;
    const int er = lane >> 2, ec = (lane & 3) * 2;
#pragma unroll
    for (int mf = 0; mf < 4; mf++)
#pragma unroll
        for (int nf = 0; nf < 4; nf++)
#pragma unroll
            for (int hh = 0; hh < 2; hh++) {
                const int m = mBase + wm*64 + mf*16 + er + hh*8;
                const int n = nBase + wn*32 + nf*8 + ec;
                float2 o;
                o.x = acc[mf][nf][hh*2+0] + bp[n];
                o.y = acc[mf][nf][hh*2+1] + bp[n+1];
                *(float2*)&outp[(size_t)m * CC + n] = o;
            }
}

// ---------------------------------------------------------------------------
// fp32 -> bf16 hi/lo split
// ---------------------------------------------------------------------------
__global__ __launch_bounds__(256)
void split_kernel(const float* __restrict__ src, __nv_bfloat16* __restrict__ hi,
                  __nv_bfloat16* __restrict__ lo, int n4)
{
    int i = blockIdx.x * blockDim.x + threadIdx.x;
    if (i >= n4) return;
    float4 v = ((const float4*)src)[i];
    __nv_bfloat16 h0 = __float2bfloat16(v.x), h1 = __float2bfloat16(v.y);
    __nv_bfloat16 h2 = __float2bfloat16(v.z), h3 = __float2bfloat16(v.w);
    __nv_bfloat16 l0 = __float2bfloat16(v.x - __bfloat162float(h0));
    __nv_bfloat16 l1 = __float2bfloat16(v.y - __bfloat162float(h1));
    __nv_bfloat16 l2 = __float2bfloat16(v.z - __bfloat162float(h2));
    __nv_bfloat16 l3 = __float2bfloat16(v.w - __bfloat162float(h3));
    __nv_bfloat162* H = (__nv_bfloat162*)hi;
    __nv_bfloat162* L = (__nv_bfloat162*)lo;
    H[2*i]   = __halves2bfloat162(h0, h1);
    H[2*i+1] = __halves2bfloat162(h2, h3);
    L[2*i]   = __halves2bfloat162(l0, l1);
    L[2*i+1] = __halves2bfloat162(l2, l3);
}

__global__ __launch_bounds__(256)
void split_w_kernel(const float* __restrict__ Wk, const float* __restrict__ Wq,
                    const float* __restrict__ Wv, const float* __restrict__ Wp)
{
    const int z = blockIdx.z;
    const float* src = (z == 0) ? Wk : (z == 1) ? Wq : (z == 2) ? Wv : Wp;
    __nv_bfloat16* hi = g_whi + (size_t)z * CC * CC;
    __nv_bfloat16* lo = g_wlo + (size_t)z * CC * CC;
    int i = blockIdx.x * blockDim.x + threadIdx.x;
    const int n4 = CC * CC / 4;
    if (i >= n4) return;
    float4 v = ((const float4*)src)[i];
    __nv_bfloat16 h0 = __float2bfloat16(v.x), h1 = __float2bfloat16(v.y);
    __nv_bfloat16 h2 = __float2bfloat16(v.z), h3 = __float2bfloat16(v.w);
    __nv_bfloat16 l0 = __float2bfloat16(v.x - __bfloat162float(h0));
    __nv_bfloat16 l1 = __float2bfloat16(v.y - __bfloat162float(h1));
    __nv_bfloat16 l2 = __float2bfloat16(v.z - __bfloat162float(h2));
    __nv_bfloat16 l3 = __float2bfloat16(v.w - __bfloat162float(h3));
    __nv_bfloat162* H = (__nv_bfloat162*)hi;
    __nv_bfloat162* L = (__nv_bfloat162*)lo;
    H[2*i]   = __halves2bfloat162(h0, h1);
    H[2*i+1] = __halves2bfloat162(h2, h3);
    L[2*i]   = __halves2bfloat162(l0, l1);
    L[2*i+1] = __halves2bfloat162(l2, l3);
}

// ---------------------------------------------------------------------------
// Causal flash attention (fp32 SIMT; epilogue writes bf16 hi/lo of y)
// ---------------------------------------------------------------------------
__global__ __launch_bounds__(256)
void flash_attn_kernel()
{
    extern __shared__ float sm[];
    float* Qs = sm;
    float* Ks = sm + 64*64;
    float* Vs = Ks + 64*65;
    float* Ps = Vs + 64*64;

    const int tid = threadIdx.x;
    const int ty = tid >> 4, tx = tid & 15;
    const int r0 = ty << 2, c0 = tx << 2;
    const int qt = blockIdx.x;
    const int bh = blockIdx.y;

    const float* Qg = g_q + (size_t)bh * TT * HD + (size_t)qt * 64 * HD;
    const float* Kg = g_k + (size_t)bh * TT * HD;
    const float* Vg = g_v + (size_t)bh * TT * HD;

    {
        int row = tid >> 4;
        int c4  = (tid & 15) << 2;
#pragma unroll
        for (int it = 0; it < 4; it++) {
            int r = row + it*16;
            float4 v = *(const float4*)&Qg[(size_t)r*HD + c4];
            v.x *= 0.125f; v.y *= 0.125f; v.z *= 0.125f; v.w *= 0.125f;
            *(float4*)&Qs[r*64 + c4] = v;
        }
    }

    float m_i[4], l_i[4], O[4][4];
#pragma unroll
    for (int i = 0; i < 4; i++) {
        m_i[i] = -INFINITY; l_i[i] = 0.f;
#pragma unroll
        for (int j = 0; j < 4; j++) O[i][j] = 0.f;
    }

    for (int kt = 0; kt <= qt; kt++) {
        __syncthreads();
        {
            int row = tid >> 4;
            int c4  = (tid & 15) << 2;
#pragma unroll
            for (int it = 0; it < 4; it++) {
                int r = row + it*16;
                size_t goff = (size_t)(kt*64 + r) * HD + c4;
                float4 kv = *(const float4*)&Kg[goff];
                Ks[r*65 + c4+0] = kv.x; Ks[r*65 + c4+1] = kv.y;
                Ks[r*65 + c4+2] = kv.z; Ks[r*65 + c4+3] = kv.w;
                float4 vv = *(const float4*)&Vg[goff];
                *(float4*)&Vs[r*64 + c4] = vv;
            }
        }
        __syncthreads();

        float S[4][4];
#pragma unroll
        for (int i = 0; i < 4; i++)
#pragma unroll
            for (int j = 0; j < 4; j++) S[i][j] = 0.f;
#pragma unroll 8
        for (int d = 0; d < 64; d++) {
            float qv[4], kv[4];
#pragma unroll
            for (int i = 0; i < 4; i++) qv[i] = Qs[(r0+i)*64 + d];
#pragma unroll
            for (int j = 0; j < 4; j++) kv[j] = Ks[(c0+j)*65 + d];
#pragma unroll
            for (int i = 0; i < 4; i++)
#pragma unroll
                for (int j = 0; j < 4; j++)
                    S[i][j] = fmaf(qv[i], kv[j], S[i][j]);
        }

        if (kt == qt) {
#pragma unroll
            for (int i = 0; i < 4; i++)
#pragma unroll
                for (int j = 0; j < 4; j++)
                    if (c0 + j > r0 + i) S[i][j] = -INFINITY;
        }

        float mloc[4];
#pragma unroll
        for (int i = 0; i < 4; i++)
            mloc[i] = fmaxf(fmaxf(S[i][0], S[i][1]), fmaxf(S[i][2], S[i][3]));
#pragma unroll
        for (int off = 1; off < 16; off <<= 1)
#pragma unroll
            for (int i = 0; i < 4; i++)
                mloc[i] = fmaxf(mloc[i], __shfl_xor_sync(0xffffffffu, mloc[i], off));

        float corr[4], rs[4];
#pragma unroll
        for (int i = 0; i < 4; i++) {
            float mn = fmaxf(m_i[i], mloc[i]);
            corr[i] = __expf(m_i[i] - mn);
            m_i[i] = mn;
        }
#pragma unroll
        for (int i = 0; i < 4; i++) {
            float s = 0.f;
#pragma unroll
            for (int j = 0; j < 4; j++) {
                float p = __expf(S[i][j] - m_i[i]);
                S[i][j] = p;
                s += p;
            }
            rs[i] = s;
        }
#pragma unroll
        for (int off = 1; off < 16; off <<= 1)
#pragma unroll
            for (int i = 0; i < 4; i++)
                rs[i] += __shfl_xor_sync(0xffffffffu, rs[i], off);
#pragma unroll
        for (int i = 0; i < 4; i++) {
            l_i[i] = l_i[i] * corr[i] + rs[i];
#pragma unroll
            for (int j = 0; j < 4; j++) O[i][j] *= corr[i];
        }

#pragma unroll
        for (int i = 0; i < 4; i++)
#pragma unroll
            for (int j = 0; j < 4; j++)
                Ps[(r0+i)*65 + c0 + j] = S[i][j];
        __syncthreads();

#pragma unroll 8
        for (int c = 0; c < 64; c++) {
            float pv[4], vv[4];
#pragma unroll
            for (int i = 0; i < 4; i++) pv[i] = Ps[(r0+i)*65 + c];
#pragma unroll
            for (int j = 0; j < 4; j++) vv[j] = Vs[c*64 + c0 + j];
#pragma unroll
            for (int i = 0; i < 4; i++)
#pragma unroll
                for (int j = 0; j < 4; j++)
                    O[i][j] = fmaf(pv[i], vv[j], O[i][j]);
        }
    }

    const int b = bh >> 4, h = bh & 15;
#pragma unroll
    for (int i = 0; i < 4; i++) {
        float inv = 1.0f / l_i[i];
        int t = qt*64 + r0 + i;
        size_t base = ((size_t)b*TT + t)*CC + h*HD + c0;
        float y0 = O[i][0]*inv, y1 = O[i][1]*inv, y2 = O[i][2]*inv, y3 = O[i][3]*inv;
        __nv_bfloat16 h0 = __float2bfloat16(y0), h1 = __float2bfloat16(y1);
        __nv_bfloat16 h2 = __float2bfloat16(y2), h3 = __float2bfloat16(y3);
        __nv_bfloat16 l0 = __float2bfloat16(y0 - __bfloat162float(h0));
        __nv_bfloat16 l1 = __float2bfloat16(y1 - __bfloat162float(h1));
        __nv_bfloat16 l2 = __float2bfloat16(y2 - __bfloat162float(h2));
        __nv_bfloat16 l3 = __float2bfloat16(y3 - __bfloat162float(h3));
        *(__nv_bfloat162*)&g_yhi[base]   = __halves2bfloat162(h0, h1);
        *(__nv_bfloat162*)&g_yhi[base+2] = __halves2bfloat162(h2, h3);
        *(__nv_bfloat162*)&g_ylo[base]   = __halves2bfloat162(l0, l1);
        *(__nv_bfloat162*)&g_ylo[base+2] = __halves2bfloat162(l2, l3);
    }
}

// ---------------------------------------------------------------------------
extern "C" void kernel_launch(void* const* d_in, const int* in_sizes, int n_in,
                              void* d_out, int out_size)
{
    const float* x  = (const float*)d_in[0];
    const float* Wk = (const float*)d_in[1];
    const float* bk = (const float*)d_in[2];
    const float* Wq = (const float*)d_in[3];
    const float* bq = (const float*)d_in[4];
    const float* Wv = (const float*)d_in[5];
    const float* bv = (const float*)d_in[6];
    const float* Wp = (const float*)d_in[7];
    const float* bp = (const float*)d_in[8];
    float* outp = (float*)d_out;

    cudaFuncSetAttribute((const void*)flash_attn_kernel,
                         cudaFuncAttributeMaxDynamicSharedMemorySize, 66048);
    cudaFuncSetAttribute((const void*)qkv_mma_kernel,
                         cudaFuncAttributeMaxDynamicSharedMemorySize, GSMEM);
    cudaFuncSetAttribute((const void*)proj_mma_kernel,
                         cudaFuncAttributeMaxDynamicSharedMemorySize, GSMEM);

    // 1. Split X and weights into bf16 hi/lo
    {
        __nv_bfloat16 *xhi, *xlo;
        cudaGetSymbolAddress((void**)&xhi, g_xhi);
        cudaGetSymbolAddress((void**)&xlo, g_xlo);
        const int n4 = BB * TT * CC / 4;
        split_kernel<<<(n4 + 255) / 256, 256>>>(x, xhi, xlo, n4);
    }
    split_w_kernel<<<dim3((CC*CC/4 + 255)/256, 1, 4), 256>>>(Wk, Wq, Wv, Wp);

    // 2. QKV projections (HMMA split-3), scatter + bias
    qkv_mma_kernel<<<dim3(8, 64, 3), 256, GSMEM>>>(bk, bq, bv);

    // 3. Causal flash attention (fp32), writes bf16 split of y
    flash_attn_kernel<<<dim3(32, 64), 256, 66048>>>();

    // 4. Output projection (HMMA split-3), bias, d_out
    proj_mma_kernel<<<dim3(8, 64), 256, GSMEM>>>(bp, outp);
}

// round 9
// speedup vs baseline: 1.5368x; 1.5368x over previous
#include <cuda_runtime.h>
#include <cuda_bf16.h>
#include <cuda_fp16.h>
#include <math.h>
#include <cstdint>

#define BB 4
#define TT 2048
#define CC 1024
#define HH 16
#define HD 64
#define GK 1024

// ---------------------------------------------------------------------------
// Device-global scratch (allocation-free per harness rules)
// ---------------------------------------------------------------------------
__device__ __half g_qhi[(size_t)BB*HH*TT*HD];   // Q split, pre-scaled 0.125*log2(e)
__device__ __half g_qlo[(size_t)BB*HH*TT*HD];
__device__ __half g_khi[(size_t)BB*HH*TT*HD];
__device__ __half g_klo[(size_t)BB*HH*TT*HD];
__device__ __half g_vhi[(size_t)BB*HH*TT*HD];
__device__ __half g_vlo[(size_t)BB*HH*TT*HD];
__device__ __nv_bfloat16 g_xhi[(size_t)BB*TT*CC];
__device__ __nv_bfloat16 g_xlo[(size_t)BB*TT*CC];
__device__ __nv_bfloat16 g_whi[(size_t)4*CC*CC];
__device__ __nv_bfloat16 g_wlo[(size_t)4*CC*CC];
__device__ __nv_bfloat16 g_yhi[(size_t)BB*TT*CC];
__device__ __nv_bfloat16 g_ylo[(size_t)BB*TT*CC];

// ---------------------------------------------------------------------------
// PTX helpers (sm_80-compatible)
// ---------------------------------------------------------------------------
__device__ __forceinline__ uint32_t smem_u32(const void* p) {
    uint32_t a;
    asm("{ .reg .u64 t; cvta.to.shared.u64 t, %1; cvt.u32.u64 %0, t; }" : "=r"(a) : "l"(p));
    return a;
}
__device__ __forceinline__ void ldsm4(uint32_t* r, uint32_t addr) {
    asm volatile("ldmatrix.sync.aligned.m8n8.x4.shared.b16 {%0,%1,%2,%3}, [%4];"
        : "=r"(r[0]), "=r"(r[1]), "=r"(r[2]), "=r"(r[3]) : "r"(addr));
}
__device__ __forceinline__ void ldsm4t(uint32_t* r, uint32_t addr) {
    asm volatile("ldmatrix.sync.aligned.m8n8.x4.trans.shared.b16 {%0,%1,%2,%3}, [%4];"
        : "=r"(r[0]), "=r"(r[1]), "=r"(r[2]), "=r"(r[3]) : "r"(addr));
}
__device__ __forceinline__ void mma_bf16(float* d, const uint32_t* a, const uint32_t* b) {
    asm volatile("mma.sync.aligned.m16n8k16.row.col.f32.bf16.bf16.f32 "
        "{%0,%1,%2,%3}, {%4,%5,%6,%7}, {%8,%9}, {%0,%1,%2,%3};"
        : "+f"(d[0]), "+f"(d[1]), "+f"(d[2]), "+f"(d[3])
        : "r"(a[0]), "r"(a[1]), "r"(a[2]), "r"(a[3]), "r"(b[0]), "r"(b[1]));
}
__device__ __forceinline__ void mma_f16(float* d, const uint32_t* a, const uint32_t* b) {
    asm volatile("mma.sync.aligned.m16n8k16.row.col.f32.f16.f16.f32 "
        "{%0,%1,%2,%3}, {%4,%5,%6,%7}, {%8,%9}, {%0,%1,%2,%3};"
        : "+f"(d[0]), "+f"(d[1]), "+f"(d[2]), "+f"(d[3])
        : "r"(a[0]), "r"(a[1]), "r"(a[2]), "r"(a[3]), "r"(b[0]), "r"(b[1]));
}
__device__ __forceinline__ void cpa16(uint32_t dst, const void* src) {
    asm volatile("cp.async.cg.shared.global [%0], [%1], 16;" :: "r"(dst), "l"(src));
}
#define CP_COMMIT() asm volatile("cp.async.commit_group;" ::: "memory")
#define CP_WAIT1()  asm volatile("cp.async.wait_group 1;" ::: "memory")
#define CP_WAIT0()  asm volatile("cp.async.wait_group 0;" ::: "memory")

// exp2 on the FMA pipe, x <= 0 (clamped at -126). err ~2e-6.
__device__ __forceinline__ float fexp2(float x) {
    x = fmaxf(x, -126.0f);
    float z  = x + 12582912.0f;
    float fi = z - 12582912.0f;
    float f  = x - fi;
    float p  = 1.3333558146428443e-3f;
    p = fmaf(p, f, 9.6181291076284772e-3f);
    p = fmaf(p, f, 5.5504108664821580e-2f);
    p = fmaf(p, f, 2.4022650695910071e-1f);
    p = fmaf(p, f, 6.9314718055994531e-1f);
    p = fmaf(p, f, 1.0f);
    return p * __int_as_float(((int)fi + 127) << 23);
}
__device__ __forceinline__ void split_pair(float a, float b, uint32_t& hi, uint32_t& lo) {
    __half2 h = __floats2half2_rn(a, b);
    float2 rr = __half22float2(h);
    __half2 l = __floats2half2_rn(a - rr.x, b - rr.y);
    hi = *reinterpret_cast<uint32_t*>(&h);
    lo = *reinterpret_cast<uint32_t*>(&l);
}

// ---------------------------------------------------------------------------
// GEMM core (unchanged, proven): 128x128, bf16 hi/lo 3-term split.
// ---------------------------------------------------------------------------
#define GSTAGE 40960
#define GSMEM  (2*GSTAGE)
#define NSTG   (GK/32)

__device__ __forceinline__ void gemm_core(
    float acc[4][4][4], char* smem,
    const __nv_bfloat16* __restrict__ Ahi, const __nv_bfloat16* __restrict__ Alo,
    const __nv_bfloat16* __restrict__ Bhi, const __nv_bfloat16* __restrict__ Blo)
{
    const int tid = threadIdx.x, lane = tid & 31, wid = tid >> 5;
    const int wm = wid >> 2, wn = wid & 3;
    const uint32_t sb = smem_u32(smem);

#pragma unroll
    for (int i = 0; i < 4; i++)
#pragma unroll
        for (int j = 0; j < 4; j++)
#pragma unroll
            for (int v = 0; v < 4; v++) acc[i][j][v] = 0.f;

    const int laneA_row = (lane & 7) + ((lane >> 3) & 1) * 8;
    const int laneA_kb  = (lane >> 4) * 16;
    const int laneB_row = (lane & 7) + (lane >> 4) * 8;
    const int laneB_kb  = ((lane >> 3) & 1) * 16;
    const uint32_t aB0 = sb + (uint32_t)(wm * 64 + laneA_row) * 80 + laneA_kb;
    const uint32_t bB0 = sb + 20480u + (uint32_t)(wn * 32 + laneB_row) * 80 + laneB_kb;

    const int lrow = tid >> 2, lseg = tid & 3;
    const uint32_t dst0 = sb + (uint32_t)lrow * 80 + lseg * 16;

    auto load_stage = [&](int s) {
        const uint32_t d = dst0 + (uint32_t)(s & 1) * GSTAGE;
        const size_t go  = (size_t)lrow * GK + (size_t)s * 32 + lseg * 8;
        const size_t go2 = go + (size_t)64 * GK;
        cpa16(d,                  Ahi + go);
        cpa16(d + 64*80,          Ahi + go2);
        cpa16(d + 10240,          Alo + go);
        cpa16(d + 10240 + 64*80,  Alo + go2);
        cpa16(d + 20480,          Bhi + go);
        cpa16(d + 20480 + 64*80,  Bhi + go2);
        cpa16(d + 30720,          Blo + go);
        cpa16(d + 30720 + 64*80,  Blo + go2);
        CP_COMMIT();
    };

    load_stage(0);

    for (int s = 0; s < NSTG; s++) {
        if (s + 1 < NSTG) { load_stage(s + 1); CP_WAIT1(); }
        else              { CP_WAIT0(); }
        __syncthreads();

        const uint32_t aB = aB0 + (uint32_t)(s & 1) * GSTAGE;
        const uint32_t bB = bB0 + (uint32_t)(s & 1) * GSTAGE;
#pragma unroll
        for (int kk = 0; kk < 2; kk++) {
            const uint32_t ko = kk * 32;
            uint32_t ah[4][4], al[4][4], bh[2][4], bl[2][4];
#pragma unroll
            for (int mf = 0; mf < 4; mf++) {
                ldsm4(ah[mf], aB + mf * 1280 + ko);
                ldsm4(al[mf], aB + 10240 + mf * 1280 + ko);
            }
#pragma unroll
            for (int p = 0; p < 2; p++) {
                ldsm4(bh[p], bB + p * 1280 + ko);
                ldsm4(bl[p], bB + 10240 + p * 1280 + ko);
            }
#pragma unroll
            for (int mf = 0; mf < 4; mf++)
#pragma unroll
                for (int nf = 0; nf < 4; nf++) {
                    uint32_t* ph = &bh[nf >> 1][(nf & 1) * 2];
                    uint32_t* pl = &bl[nf >> 1][(nf & 1) * 2];
                    mma_bf16(acc[mf][nf], ah[mf], ph);
                    mma_bf16(acc[mf][nf], al[mf], ph);
                    mma_bf16(acc[mf][nf], ah[mf], pl);
                }
        }
        __syncthreads();
    }
}

// ---------------------------------------------------------------------------
// GEMM A: fused QKV; epilogue writes fp16 hi/lo of q/k/v (Q pre-scaled).
// ---------------------------------------------------------------------------
__global__ __launch_bounds__(256, 1)
void qkv_mma_kernel(const float* __restrict__ bk, const float* __restrict__ bq,
                    const float* __restrict__ bv)
{
    extern __shared__ char smem[];
    const int z = blockIdx.z;
    const float* bias; __half* ohi; __half* olo; float sc;
    if (z == 0)      { bias = bk; ohi = g_khi; olo = g_klo; sc = 1.f; }
    else if (z == 1) { bias = bq; ohi = g_qhi; olo = g_qlo; sc = 0.18033688011112042f; }
    else             { bias = bv; ohi = g_vhi; olo = g_vlo; sc = 1.f; }

    const int mBase = blockIdx.y << 7;
    const int nBase = blockIdx.x << 7;

    float acc[4][4][4];
    gemm_core(acc, smem,
        g_xhi + (size_t)mBase * GK, g_xlo + (size_t)mBase * GK,
        g_whi + (size_t)z * CC * CC + (size_t)nBase * GK,
        g_wlo + (size_t)z * CC * CC + (size_t)nBase * GK);

    const int lane = threadIdx.x & 31, wid = threadIdx.x >> 5;
    const int wm = wid >> 2, wn = wid & 3;
    const int er = lane >> 2, ec = (lane & 3) * 2;
#pragma unroll
    for (int mf = 0; mf < 4; mf++)
#pragma unroll
        for (int nf = 0; nf < 4; nf++)
#pragma unroll
            for (int hh = 0; hh < 2; hh++) {
                const int m = mBase + wm*64 + mf*16 + er + hh*8;
                const int n = nBase + wn*32 + nf*8 + ec;
                const int bb = m >> 11, t = m & (TT - 1);
                const int hd = n >> 6, d = n & 63;
                float v0 = (acc[mf][nf][hh*2+0] + bias[n])   * sc;
                float v1 = (acc[mf][nf][hh*2+1] + bias[n+1]) * sc;
                __half h0 = __float2half_rn(v0), h1 = __float2half_rn(v1);
                __half l0 = __float2half_rn(v0 - __half2float(h0));
                __half l1 = __float2half_rn(v1 - __half2float(h1));
                size_t idx = (((size_t)bb*HH + hd)*TT + t)*HD + d;
                *(__half2*)&ohi[idx] = __halves2half2(h0, h1);
                *(__half2*)&olo[idx] = __halves2half2(l0, l1);
            }
}

// ---------------------------------------------------------------------------
// GEMM B: output projection (unchanged).
// ---------------------------------------------------------------------------
__global__ __launch_bounds__(256, 1)
void proj_mma_kernel(const float* __restrict__ bp, float* __restrict__ outp)
{
    extern __shared__ char smem[];
    const int mBase = blockIdx.y << 7;
    const int nBase = blockIdx.x << 7;

    float acc[4][4][4];
    gemm_core(acc, smem,
        g_yhi + (size_t)mBase * GK, g_ylo + (size_t)mBase * GK,
        g_whi + (size_t)3 * CC * CC + (size_t)nBase * GK,
        g_wlo + (size_t)3 * CC * CC + (size_t)nBase * GK);

    const int lane = threadIdx.x & 31, wid = threadIdx.x >> 5;
    const int wm = wid >> 2, wn = wid & 3;
    const int er = lane >> 2, ec = (lane & 3) * 2;
#pragma unroll
    for (int mf = 0; mf < 4; mf++)
#pragma unroll
        for (int nf = 0; nf < 4; nf++)
#pragma unroll
            for (int hh = 0; hh < 2; hh++) {
                const int m = mBase + wm*64 + mf*16 + er + hh*8;
                const int n = nBase + wn*32 + nf*8 + ec;
                float2 o;
                o.x = acc[mf][nf][hh*2+0] + bp[n];
                o.y = acc[mf][nf][hh*2+1] + bp[n+1];
                *(float2*)&outp[(size_t)m * CC + n] = o;
            }
}

// ---------------------------------------------------------------------------
// fp32 -> bf16 hi/lo splits (X and weights)
// ---------------------------------------------------------------------------
__global__ __launch_bounds__(256)
void split_kernel(const float* __restrict__ src, __nv_bfloat16* __restrict__ hi,
                  __nv_bfloat16* __restrict__ lo, int n4)
{
    int i = blockIdx.x * blockDim.x + threadIdx.x;
    if (i >= n4) return;
    float4 v = ((const float4*)src)[i];
    __nv_bfloat16 h0 = __float2bfloat16(v.x), h1 = __float2bfloat16(v.y);
    __nv_bfloat16 h2 = __float2bfloat16(v.z), h3 = __float2bfloat16(v.w);
    __nv_bfloat16 l0 = __float2bfloat16(v.x - __bfloat162float(h0));
    __nv_bfloat16 l1 = __float2bfloat16(v.y - __bfloat162float(h1));
    __nv_bfloat16 l2 = __float2bfloat16(v.z - __bfloat162float(h2));
    __nv_bfloat16 l3 = __float2bfloat16(v.w - __bfloat162float(h3));
    __nv_bfloat162* H = (__nv_bfloat162*)hi;
    __nv_bfloat162* L = (__nv_bfloat162*)lo;
    H[2*i]   = __halves2bfloat162(h0, h1);
    H[2*i+1] = __halves2bfloat162(h2, h3);
    L[2*i]   = __halves2bfloat162(l0, l1);
    L[2*i+1] = __halves2bfloat162(l2, l3);
}

__global__ __launch_bounds__(256)
void split_w_kernel(const float* __restrict__ Wk, const float* __restrict__ Wq,
                    const float* __restrict__ Wv, const float* __restrict__ Wp)
{
    const int z = blockIdx.z;
    const float* src = (z == 0) ? Wk : (z == 1) ? Wq : (z == 2) ? Wv : Wp;
    __nv_bfloat16* hi = g_whi + (size_t)z * CC * CC;
    __nv_bfloat16* lo = g_wlo + (size_t)z * CC * CC;
    int i = blockIdx.x * blockDim.x + threadIdx.x;
    const int n4 = CC * CC / 4;
    if (i >= n4) return;
    float4 v = ((const float4*)src)[i];
    __nv_bfloat16 h0 = __float2bfloat16(v.x), h1 = __float2bfloat16(v.y);
    __nv_bfloat16 h2 = __float2bfloat16(v.z), h3 = __float2bfloat16(v.w);
    __nv_bfloat16 l0 = __float2bfloat16(v.x - __bfloat162float(h0));
    __nv_bfloat16 l1 = __float2bfloat16(v.y - __bfloat162float(h1));
    __nv_bfloat16 l2 = __float2bfloat16(v.z - __bfloat162float(h2));
    __nv_bfloat16 l3 = __float2bfloat16(v.w - __bfloat162float(h3));
    __nv_bfloat162* H = (__nv_bfloat162*)hi;
    __nv_bfloat162* L = (__nv_bfloat162*)lo;
    H[2*i]   = __halves2bfloat162(h0, h1);
    H[2*i+1] = __halves2bfloat162(h2, h3);
    L[2*i]   = __halves2bfloat162(l0, l1);
    L[2*i+1] = __halves2bfloat162(l2, l3);
}

// ---------------------------------------------------------------------------
// Tensor-core causal flash attention. BM=128 (4 warps x 32 rows), BN=64.
// fp16 hi/lo 3-term split MMA, base-2 online softmax (FMA exp2).
// Rows padded to 144 B. K/V double-buffered cp.async.
// smem: Qhi|Qlo (18432 each) + 2 stages x [Khi|Klo|Vhi|Vlo] (9216 each)
// ---------------------------------------------------------------------------
#define FSMEM (36864 + 2*36864)   // 110592

__global__ __launch_bounds__(128, 2)
void flash_mma_kernel()
{
    extern __shared__ char fsm[];
    const uint32_t sb = smem_u32(fsm);
    const int tid = threadIdx.x, lane = tid & 31, w = tid >> 5;
    const int qt = (TT/128 - 1) - (int)blockIdx.x;   // longest first
    const int bh = blockIdx.y;
    const int ktmax = 2 * qt + 1;

    const size_t headoff = (size_t)bh * TT * HD;
    const uint32_t sQhi = sb, sQlo = sb + 18432;
    const uint32_t sStage = sb + 36864;

    // Q: one 128-B row per thread (hi + lo)
    {
        const __half* qh = g_qhi + headoff + ((size_t)qt * 128 + tid) * HD;
        const __half* ql = g_qlo + headoff + ((size_t)qt * 128 + tid) * HD;
        uint32_t dh = sQhi + tid * 144, dl = sQlo + tid * 144;
#pragma unroll
        for (int s2 = 0; s2 < 8; s2++) {
            cpa16(dh + s2 * 16, qh + s2 * 8);
            cpa16(dl + s2 * 16, ql + s2 * 8);
        }
    }
    const int kvrow = tid & 63;
    const int kvsel = tid >> 6;   // 0 -> K pair, 1 -> V pair
    const __half* srcH = (kvsel ? g_vhi : g_khi) + headoff;
    const __half* srcL = (kvsel ? g_vlo : g_klo) + headoff;
    {
        const __half* sh = srcH + (size_t)kvrow * HD;
        const __half* sl = srcL + (size_t)kvrow * HD;
        uint32_t dh = sStage + kvsel * 18432 + kvrow * 144;
#pragma unroll
        for (int s2 = 0; s2 < 8; s2++) {
            cpa16(dh + s2 * 16, sh + s2 * 8);
            cpa16(dh + 9216 + s2 * 16, sl + s2 * 8);
        }
    }
    CP_COMMIT();

    float accO[2][8][4];
#pragma unroll
    for (int i = 0; i < 2; i++)
#pragma unroll
        for (int j = 0; j < 8; j++)
#pragma unroll
            for (int e = 0; e < 4; e++) accO[i][j][e] = 0.f;
    float m_i[2][2] = {{-1e30f, -1e30f}, {-1e30f, -1e30f}};
    float l_i[2][2] = {{0.f, 0.f}, {0.f, 0.f}};

    const int r = lane >> 2, c0 = (lane & 3) * 2;
    const uint32_t aoff = (uint32_t)((lane & 7) + ((lane >> 3) & 1) * 8) * 144 + (lane >> 4) * 16;
    const uint32_t boff = (uint32_t)((lane & 7) + (lane >> 4) * 8) * 144 + ((lane >> 3) & 1) * 16;

    for (int kt = 0; kt <= ktmax; kt++) {
        const int s = kt & 1;
        if (kt < ktmax) {
            const __half* sh = srcH + (size_t)((kt + 1) * 64 + kvrow) * HD;
            const __half* sl = srcL + (size_t)((kt + 1) * 64 + kvrow) * HD;
            uint32_t dh = sStage + (s ^ 1) * 36864 + kvsel * 18432 + kvrow * 144;
#pragma unroll
            for (int s2 = 0; s2 < 8; s2++) {
                cpa16(dh + s2 * 16, sh + s2 * 8);
                cpa16(dh + 9216 + s2 * 16, sl + s2 * 8);
            }
            CP_COMMIT();
            CP_WAIT1();
        } else {
            CP_WAIT0();
        }
        __syncthreads();

        const uint32_t stK = sStage + s * 36864;
        const uint32_t stV = stK + 18432;

        // ---- S = Q K^T (3-term fp16 split), base-2 units ----
        float S[2][8][4];
#pragma unroll
        for (int i = 0; i < 2; i++)
#pragma unroll
            for (int j = 0; j < 8; j++)
#pragma unroll
                for (int e = 0; e < 4; e++) S[i][j][e] = 0.f;

#pragma unroll
        for (int kc = 0; kc < 4; kc++) {
            uint32_t aQh[2][4], aQl[2][4];
#pragma unroll
            for (int mf = 0; mf < 2; mf++) {
                uint32_t ad = (uint32_t)(w * 32 + mf * 16) * 144 + kc * 32 + aoff;
                ldsm4(aQh[mf], sQhi + ad);
                ldsm4(aQl[mf], sQlo + ad);
            }
#pragma unroll
            for (int np = 0; np < 4; np++) {
                uint32_t bKh[4], bKl[4];
                uint32_t bd = (uint32_t)(np * 16) * 144 + kc * 32 + boff;
                ldsm4(bKh, stK + bd);
                ldsm4(bKl, stK + 9216 + bd);
#pragma unroll
                for (int mf = 0; mf < 2; mf++)
#pragma unroll
                    for (int o = 0; o < 2; o++) {
                        float* dd = S[mf][np * 2 + o];
                        mma_f16(dd, aQh[mf], &bKh[o * 2]);
                        mma_f16(dd, aQl[mf], &bKh[o * 2]);
                        mma_f16(dd, aQh[mf], &bKl[o * 2]);
                    }
            }
        }

        // ---- causal mask (only near the diagonal) ----
        if (kt >= 2 * qt) {
#pragma unroll
            for (int mf = 0; mf < 2; mf++)
#pragma unroll
                for (int nf = 0; nf < 8; nf++)
#pragma unroll
                    for (int e = 0; e < 4; e++) {
                        int row = qt * 128 + w * 32 + mf * 16 + r + (e >> 1) * 8;
                        int col = kt * 64 + nf * 8 + c0 + (e & 1);
                        if (col > row) S[mf][nf][e] = -1e30f;
                    }
        }

        // ---- online softmax (base 2) ----
#pragma unroll
        for (int mf = 0; mf < 2; mf++)
#pragma unroll
            for (int hh = 0; hh < 2; hh++) {
                float mx = -1e30f;
#pragma unroll
                for (int nf = 0; nf < 8; nf++)
                    mx = fmaxf(mx, fmaxf(S[mf][nf][hh*2], S[mf][nf][hh*2+1]));
                mx = fmaxf(mx, __shfl_xor_sync(0xffffffffu, mx, 1));
                mx = fmaxf(mx, __shfl_xor_sync(0xffffffffu, mx, 2));
                float mo = m_i[mf][hh];
                float mn = fmaxf(mo, mx);
                float corr = fexp2(mo - mn);
                m_i[mf][hh] = mn;
                float rs = 0.f;
#pragma unroll
                for (int nf = 0; nf < 8; nf++) {
                    float p0 = fexp2(S[mf][nf][hh*2]   - mn);
                    float p1 = fexp2(S[mf][nf][hh*2+1] - mn);
                    S[mf][nf][hh*2] = p0; S[mf][nf][hh*2+1] = p1;
                    rs += p0 + p1;
                }
                rs += __shfl_xor_sync(0xffffffffu, rs, 1);
                rs += __shfl_xor_sync(0xffffffffu, rs, 2);
                l_i[mf][hh] = l_i[mf][hh] * corr + rs;
#pragma unroll
                for (int nf = 0; nf < 8; nf++) {
                    accO[mf][nf][hh*2]   *= corr;
                    accO[mf][nf][hh*2+1] *= corr;
                }
            }

        // ---- O += P V (3-term; P frags from S accumulators) ----
#pragma unroll
        for (int kc = 0; kc < 4; kc++) {
            uint32_t ph[2][4], pl[2][4];
#pragma unroll
            for (int mf = 0; mf < 2; mf++) {
                split_pair(S[mf][2*kc][0],   S[mf][2*kc][1],   ph[mf][0], pl[mf][0]);
                split_pair(S[mf][2*kc][2],   S[mf][2*kc][3],   ph[mf][1], pl[mf][1]);
                split_pair(S[mf][2*kc+1][0], S[mf][2*kc+1][1], ph[mf][2], pl[mf][2]);
                split_pair(S[mf][2*kc+1][2], S[mf][2*kc+1][3], ph[mf][3], pl[mf][3]);
            }
#pragma unroll
            for (int np = 0; np < 4; np++) {
                uint32_t vh_[4], vl_[4];
                uint32_t vd = (uint32_t)(kc * 16) * 144 + np * 32 + aoff;
                ldsm4t(vh_, stV + vd);
                ldsm4t(vl_, stV + 9216 + vd);
#pragma unroll
                for (int mf = 0; mf < 2; mf++)
#pragma unroll
                    for (int o = 0; o < 2; o++) {
                        float* dd = accO[mf][np * 2 + o];
                        mma_f16(dd, ph[mf], &vh_[o * 2]);
                        mma_f16(dd, pl[mf], &vh_[o * 2]);
                        mma_f16(dd, ph[mf], &vl_[o * 2]);
                    }
            }
        }
        __syncthreads();
    }

    // ---- epilogue: y = O/l -> bf16 hi/lo split ----
    const int b = bh >> 4, h = bh & 15;
#pragma unroll
    for (int mf = 0; mf < 2; mf++)
#pragma unroll
        for (int hh = 0; hh < 2; hh++) {
            float inv = 1.0f / l_i[mf][hh];
            int t = qt * 128 + w * 32 + mf * 16 + r + hh * 8;
#pragma unroll
            for (int nf = 0; nf < 8; nf++) {
                int d = nf * 8 + c0;
                size_t base = ((size_t)b * TT + t) * CC + h * 64 + d;
                float y0 = accO[mf][nf][hh*2]   * inv;
                float y1 = accO[mf][nf][hh*2+1] * inv;
                __nv_bfloat16 b0 = __float2bfloat16(y0), b1 = __float2bfloat16(y1);
                __nv_bfloat16 l0 = __float2bfloat16(y0 - __bfloat162float(b0));
                __nv_bfloat16 l1 = __float2bfloat16(y1 - __bfloat162float(b1));
                *(__nv_bfloat162*)&g_yhi[base] = __halves2bfloat162(b0, b1);
                *(__nv_bfloat162*)&g_ylo[base] = __halves2bfloat162(l0, l1);
            }
        }
}

// ---------------------------------------------------------------------------
extern "C" void kernel_launch(void* const* d_in, const int* in_sizes, int n_in,
                              void* d_out, int out_size)
{
    const float* x  = (const float*)d_in[0];
    const float* Wk = (const float*)d_in[1];
    const float* bk = (const float*)d_in[2];
    const float* Wq = (const float*)d_in[3];
    const float* bq = (const float*)d_in[4];
    const float* Wv = (const float*)d_in[5];
    const float* bv = (const float*)d_in[6];
    const float* Wp = (const float*)d_in[7];
    const float* bp = (const float*)d_in[8];
    float* outp = (float*)d_out;

    cudaFuncSetAttribute((const void*)qkv_mma_kernel,
                         cudaFuncAttributeMaxDynamicSharedMemorySize, GSMEM);
    cudaFuncSetAttribute((const void*)proj_mma_kernel,
                         cudaFuncAttributeMaxDynamicSharedMemorySize, GSMEM);
    cudaFuncSetAttribute((const void*)flash_mma_kernel,
                         cudaFuncAttributeMaxDynamicSharedMemorySize, FSMEM);

    // 1. Splits
    {
        __nv_bfloat16 *xhi, *xlo;
        cudaGetSymbolAddress((void**)&xhi, g_xhi);
        cudaGetSymbolAddress((void**)&xlo, g_xlo);
        const int n4 = BB * TT * CC / 4;
        split_kernel<<<(n4 + 255) / 256, 256>>>(x, xhi, xlo, n4);
    }
    split_w_kernel<<<dim3((CC*CC/4 + 255)/256, 1, 4), 256>>>(Wk, Wq, Wv, Wp);

    // 2. QKV projections -> fp16 hi/lo q,k,v
    qkv_mma_kernel<<<dim3(8, 64, 3), 256, GSMEM>>>(bk, bq, bv);

    // 3. Tensor-core causal flash attention -> bf16 hi/lo y
    flash_mma_kernel<<<dim3(TT/128, 64), 128, FSMEM>>>();

    // 4. Output projection -> d_out
    proj_mma_kernel<<<dim3(8, 64), 256, GSMEM>>>(bp, outp);
}